// round 1
// baseline (speedup 1.0000x reference)
#include <cuda_runtime.h>
#include <cuda_bf16.h>

// qpNet: z = max(-(x @ W^T + b), -1/EPS), EPS=1e-3  =>  z = -min(h, 1000)
// x: [B,5] f32, W: [5,5] f32, b: [5] f32, out: [B,5] f32. B = 4194304.
// Pure memory-bound elementwise-per-row op. Each thread handles 4 rows
// (20 floats = 5 x float4), fully vectorized loads/stores.

#define NEG_CLAMP (-1000.0f)   // -1/EPS

__global__ __launch_bounds__(256) void qp_kernel(
    const float* __restrict__ x,
    const float* __restrict__ W,
    const float* __restrict__ b,
    float* __restrict__ out)
{
    // Load tiny W [5,5] and b [5] — cached in L1/L2, amortized.
    float w[5][5], bb[5];
#pragma unroll
    for (int j = 0; j < 5; j++) {
        bb[j] = __ldg(b + j);
#pragma unroll
        for (int k = 0; k < 5; k++)
            w[j][k] = __ldg(W + j * 5 + k);
    }

    // Each thread: 4 rows starting at row 4*tid. base float offset = 20*tid,
    // byte offset = 80*tid -> 16B aligned, so float4 loads are legal.
    long long tid = (long long)blockIdx.x * blockDim.x + threadIdx.x;
    long long base = tid * 20;

    const float4* xin = reinterpret_cast<const float4*>(x + base);
    float4 v0 = xin[0];
    float4 v1 = xin[1];
    float4 v2 = xin[2];
    float4 v3 = xin[3];
    float4 v4 = xin[4];

    float xr[4][5];
    xr[0][0] = v0.x; xr[0][1] = v0.y; xr[0][2] = v0.z; xr[0][3] = v0.w; xr[0][4] = v1.x;
    xr[1][0] = v1.y; xr[1][1] = v1.z; xr[1][2] = v1.w; xr[1][3] = v2.x; xr[1][4] = v2.y;
    xr[2][0] = v2.z; xr[2][1] = v2.w; xr[2][2] = v3.x; xr[2][3] = v3.y; xr[2][4] = v3.z;
    xr[3][0] = v3.w; xr[3][1] = v4.x; xr[3][2] = v4.y; xr[3][3] = v4.z; xr[3][4] = v4.w;

    float zr[4][5];
#pragma unroll
    for (int r = 0; r < 4; r++) {
#pragma unroll
        for (int j = 0; j < 5; j++) {
            float h = bb[j];
#pragma unroll
            for (int k = 0; k < 5; k++)
                h = fmaf(xr[r][k], w[j][k], h);
            // z = max(-h, -1000) == -min(h, 1000)
            zr[r][j] = fmaxf(-h, NEG_CLAMP);
        }
    }

    float4 o0 = make_float4(zr[0][0], zr[0][1], zr[0][2], zr[0][3]);
    float4 o1 = make_float4(zr[0][4], zr[1][0], zr[1][1], zr[1][2]);
    float4 o2 = make_float4(zr[1][3], zr[1][4], zr[2][0], zr[2][1]);
    float4 o3 = make_float4(zr[2][2], zr[2][3], zr[2][4], zr[3][0]);
    float4 o4 = make_float4(zr[3][1], zr[3][2], zr[3][3], zr[3][4]);

    float4* oout = reinterpret_cast<float4*>(out + base);
    oout[0] = o0;
    oout[1] = o1;
    oout[2] = o2;
    oout[3] = o3;
    oout[4] = o4;
}

extern "C" void kernel_launch(void* const* d_in, const int* in_sizes, int n_in,
                              void* d_out, int out_size)
{
    const float* x = (const float*)d_in[0];   // [B,5]
    const float* W = (const float*)d_in[1];   // [5,5]
    const float* b = (const float*)d_in[2];   // [5]
    float* out = (float*)d_out;               // [B,5]

    const int B = in_sizes[0] / 5;            // 4194304
    const int rows_per_thread = 4;
    const int threads = 256;
    const long long n_threads = (long long)B / rows_per_thread;  // 1048576
    const int blocks = (int)((n_threads + threads - 1) / threads); // 4096

    qp_kernel<<<blocks, threads>>>(x, W, b, out);
}